// round 6
// baseline (speedup 1.0000x reference)
#include <cuda_runtime.h>

#define FULL 0xffffffffu
constexpr int NW = 10;   // wires
constexpr int NL = 4;    // layers

// Layer-1 fused gate bases: G = RY(th) * RZ(phi) (om pushed into phase tables)
__device__ float4 g_rot[NW * 2];
// Layers 2-4 RY coefficients: (cos(th/2), sin(th/2))
__device__ float2 g_rycs[3 * NW];
// Phase tables Gamma_g. g=1 applied in layout A, g=0,2 applied in layout B
// (storage permuted accordingly at prep). Entry idx = (k<<5)|lane, halves h=0,1.
//  g_phA = (cr0, cr1, -ci0, -ci1),  g_phB = (ci0, ci1)
__device__ float4 g_phA[3 * 512];
__device__ float2 g_phB[3 * 512];

// ---------------------------------------------------------------------------
// Prep: gate matrices + composed diagonal phase tables. One block, 1024 thr.
// ---------------------------------------------------------------------------
__global__ void prep_kernel(const float* __restrict__ w) {
    __shared__ float s_ang[1024], s_co[1024], s_si[1024];
    int v = threadIdx.x;

    if (v < NL * NW) {
        int l = v / NW, wi = v % NW;
        float phi = w[v * 3 + 0], th = w[v * 3 + 1];
        float s, c;
        sincosf(0.5f * th, &s, &c);
        if (l == 0) {
            float sp, cp;  // e^{-i phi/2} = cp + i sp
            sincosf(-0.5f * phi, &sp, &cp);
            // G = RY(th) RZ(phi)
            g_rot[wi * 2 + 0] = make_float4(c * cp, c * sp, -s * cp, s * sp);
            g_rot[wi * 2 + 1] = make_float4(s * cp, s * sp, c * cp, -c * sp);
        } else {
            g_rycs[(l - 1) * NW + wi] = make_float2(c, s);
        }
    }

    for (int g = 0; g < 3; ++g) {
        __syncthreads();
        // delta1 (RZ(om) of layer g) pushed through ring r=g+1: tmp[pi(u)] = a1(u)
        float a1 = 0.0f;
#pragma unroll
        for (int wi = 0; wi < NW; ++wi) {
            float om = w[(g * NW + wi) * 3 + 2];
            a1 += (((v >> (9 - wi)) & 1) ? 0.5f : -0.5f) * om;
        }
        int u = v, r = g + 1;
#pragma unroll
        for (int wi = 0; wi < NW; ++wi) {
            int pc = 9 - wi, pt = 9 - ((wi + r) % NW);
            if ((u >> pc) & 1) u ^= (1 << pt);
        }
        s_ang[u] = a1;
        __syncthreads();
        // add delta2 (RZ(phi) of layer g+1)
        float a = s_ang[v];
#pragma unroll
        for (int wi = 0; wi < NW; ++wi) {
            float phi = w[((g + 1) * NW + wi) * 3 + 0];
            a += (((v >> (9 - wi)) & 1) ? 0.5f : -0.5f) * phi;
        }
        float si, co;
        sincosf(a, &si, &co);
        s_co[v] = co;
        s_si[v] = si;
        __syncthreads();
        if (v < 512) {
            int k = v & 15, L = v >> 4;
            int v0, v1;
            if (g == 1) {           // layout A: v = L<<5 | k<<1 | h
                v0 = (L << 5) | (k << 1);
                v1 = v0 | 1;
            } else {                // layout B: v = k<<6 | h<<5 | L
                v0 = (k << 6) | L;
                v1 = v0 | 32;
            }
            int idx = (k << 5) | L;
            g_phA[g * 512 + idx] = make_float4(s_co[v0], s_co[v1], -s_si[v0], -s_si[v1]);
            g_phB[g * 512 + idx] = make_float2(s_si[v0], s_si[v1]);
        }
    }
}

// ---------------------------------------------------------------------------
// Packed f32x2 helpers
// ---------------------------------------------------------------------------
__device__ __forceinline__ float2 f2fma(float2 a, float2 b, float2 c) {
    float2 d;
    asm("{\n\t"
        ".reg .b64 ra, rb, rc, rd;\n\t"
        "mov.b64 ra, {%2, %3};\n\t"
        "mov.b64 rb, {%4, %5};\n\t"
        "mov.b64 rc, {%6, %7};\n\t"
        "fma.rn.f32x2 rd, ra, rb, rc;\n\t"
        "mov.b64 {%0, %1}, rd;\n\t"
        "}"
        : "=f"(d.x), "=f"(d.y)
        : "f"(a.x), "f"(a.y), "f"(b.x), "f"(b.y), "f"(c.x), "f"(c.y));
    return d;
}
__device__ __forceinline__ float2 f2mul(float2 a, float2 b) {
    float2 d;
    asm("{\n\t"
        ".reg .b64 ra, rb, rd;\n\t"
        "mov.b64 ra, {%2, %3};\n\t"
        "mov.b64 rb, {%4, %5};\n\t"
        "mul.rn.f32x2 rd, ra, rb;\n\t"
        "mov.b64 {%0, %1}, rd;\n\t"
        "}"
        : "=f"(d.x), "=f"(d.y)
        : "f"(a.x), "f"(a.y), "f"(b.x), "f"(b.y));
    return d;
}
__device__ __forceinline__ float2 pk(float v) { return make_float2(v, v); }
__device__ __forceinline__ float2 swp(float2 v) { return make_float2(v.y, v.x); }

__device__ __forceinline__ float2 shx2(float2 v, int mask) {
    float2 r;
    r.x = __shfl_xor_sync(FULL, v.x, mask);
    r.y = __shfl_xor_sync(FULL, v.y, mask);
    return r;
}
__device__ __forceinline__ float2 shidx2(float2 v, int src) {
    float2 r;
    r.x = __shfl_sync(FULL, v.x, src);
    r.y = __shfl_sync(FULL, v.y, src);
    return r;
}

// ---------------------------------------------------------------------------
// Layout (label space): label amp bit for label-wire W is p = 9 - W.
//   bits 9..5 -> lane bits, bits 4..1 -> register index, bit 0 -> packed half
// Layout A: physical wire = label. Layout B: physical wire = (label+5)%10.
// Transpose swaps the two 5-bit halves (A <-> B); it is an involution.
// ---------------------------------------------------------------------------

// 5-stage warp transpose: swap lane bit b with local slot bit b (b=0..4).
__device__ __forceinline__ void transpose(float2 RE[16], float2 IM[16], int lane) {
    // stage 0: lane bit 0 <-> half bit
    {
        bool lb = lane & 1;
#pragma unroll
        for (int k = 0; k < 16; ++k) {
            float sR = lb ? RE[k].x : RE[k].y;
            sR = __shfl_xor_sync(FULL, sR, 1);
            if (lb) RE[k].x = sR; else RE[k].y = sR;
            float sI = lb ? IM[k].x : IM[k].y;
            sI = __shfl_xor_sync(FULL, sI, 1);
            if (lb) IM[k].x = sI; else IM[k].y = sI;
        }
    }
    // stages b=1..4: lane bit b <-> reg bit b-1
#pragma unroll
    for (int b = 1; b < 5; ++b) {
        const int km = 1 << (b - 1);
        bool lb = (lane >> b) & 1;
#pragma unroll
        for (int k = 0; k < 16; ++k) {
            if (!(k & km)) {
                const int j = k | km;
                float2 sR = lb ? RE[k] : RE[j];
                sR = shx2(sR, 1 << b);
                if (lb) RE[k] = sR; else RE[j] = sR;
                float2 sI = lb ? IM[k] : IM[j];
                sI = shx2(sI, 1 << b);
                if (lb) IM[k] = sI; else IM[j] = sI;
            }
        }
    }
}

// General complex 2x2 on label wire W (local paths only used: W=5..9)
template <int W>
__device__ __forceinline__ void applyMat(float2 RE[16], float2 IM[16],
                                         float2 U00, float2 U01, float2 U10, float2 U11) {
    constexpr int p = 9 - W;
    static_assert(p <= 4, "only local gates");
    if constexpr (p >= 1) {
        constexpr int kb = 1 << (p - 1);
        const float2 u00x = pk(U00.x), u00y = pk(U00.y), nu00y = pk(-U00.y);
        const float2 u01x = pk(U01.x), u01y = pk(U01.y), nu01y = pk(-U01.y);
        const float2 u10x = pk(U10.x), u10y = pk(U10.y), nu10y = pk(-U10.y);
        const float2 u11x = pk(U11.x), u11y = pk(U11.y), nu11y = pk(-U11.y);
#pragma unroll
        for (int k = 0; k < 16; ++k) {
            if (!(k & kb)) {
                const int j = k | kb;
                float2 a0re = RE[k], a0im = IM[k], a1re = RE[j], a1im = IM[j];
                RE[k] = f2fma(nu01y, a1im, f2fma(u01x, a1re, f2fma(nu00y, a0im, f2mul(u00x, a0re))));
                IM[k] = f2fma(u01y, a1re, f2fma(u01x, a1im, f2fma(u00y, a0re, f2mul(u00x, a0im))));
                RE[j] = f2fma(nu11y, a1im, f2fma(u11x, a1re, f2fma(nu10y, a0im, f2mul(u10x, a0re))));
                IM[j] = f2fma(u11y, a1re, f2fma(u11x, a1im, f2fma(u10y, a0re, f2mul(u10x, a0im))));
            }
        }
    } else {
        // p == 0: halves pair within each register; pack rows (U00|U10) per half
        const float2 c00x = make_float2(U00.x, U10.x), c00y = make_float2(U00.y, U10.y);
        const float2 c01x = make_float2(U01.x, U11.x), c01y = make_float2(U01.y, U11.y);
        const float2 n00y = make_float2(-U00.y, -U10.y), n01y = make_float2(-U01.y, -U11.y);
#pragma unroll
        for (int k = 0; k < 16; ++k) {
            float a0r = RE[k].x, a0i = IM[k].x, a1r = RE[k].y, a1i = IM[k].y;
            float2 nre = f2fma(n01y, pk(a1i), f2fma(c01x, pk(a1r),
                          f2fma(n00y, pk(a0i), f2mul(c00x, pk(a0r)))));
            float2 nim = f2fma(c01y, pk(a1r), f2fma(c01x, pk(a1i),
                          f2fma(c00y, pk(a0r), f2mul(c00x, pk(a0i)))));
            RE[k] = nre; IM[k] = nim;
        }
    }
}

// Real RY on label wire W (local only: W=5..9)
template <int W>
__device__ __forceinline__ void ryGate(float2 RE[16], float2 IM[16], float c, float s) {
    constexpr int p = 9 - W;
    static_assert(p <= 4, "only local gates");
    if constexpr (p >= 1) {
        constexpr int kb = 1 << (p - 1);
        const float2 cp = pk(c), sp = pk(s), np = pk(-s);
#pragma unroll
        for (int k = 0; k < 16; ++k) {
            if (!(k & kb)) {
                const int j = k | kb;
                float2 a0re = RE[k], a0im = IM[k], a1re = RE[j], a1im = IM[j];
                RE[k] = f2fma(cp, a0re, f2mul(np, a1re));
                IM[k] = f2fma(cp, a0im, f2mul(np, a1im));
                RE[j] = f2fma(cp, a1re, f2mul(sp, a0re));
                IM[j] = f2fma(cp, a1im, f2mul(sp, a0im));
            }
        }
    } else {
        // p == 0: half-swap butterfly
        const float2 cp = pk(c), ss = make_float2(-s, s);
#pragma unroll
        for (int k = 0; k < 16; ++k) {
            RE[k] = f2fma(cp, RE[k], f2mul(ss, swp(RE[k])));
            IM[k] = f2fma(cp, IM[k], f2mul(ss, swp(IM[k])));
        }
    }
}

// Gamma (composed diagonal): coalesced table loads
__device__ __forceinline__ void applyPhase(float2 RE[16], float2 IM[16], int lane, int g) {
    const float4* __restrict__ A = g_phA + g * 512 + lane;
    const float2* __restrict__ Bv = g_phB + g * 512 + lane;
#pragma unroll
    for (int k = 0; k < 16; ++k) {
        float4 a = A[k << 5];
        float2 ci = Bv[k << 5];
        float2 cr = make_float2(a.x, a.y), nci = make_float2(a.z, a.w);
        float2 nre = f2fma(cr, RE[k], f2mul(nci, IM[k]));
        float2 nim = f2fma(cr, IM[k], f2mul(ci, RE[k]));
        RE[k] = nre; IM[k] = nim;
    }
}

// ---------------------------------------------------------------------------
// CNOT (label-space wires)
// ---------------------------------------------------------------------------
template <int CW, int TW>
__device__ __forceinline__ void cnotGate(float2 RE[16], float2 IM[16], int lane) {
    constexpr int pc = 9 - CW, pt = 9 - TW;
    if constexpr (pc >= 1 && pc <= 4 && pt >= 1 && pt <= 4) {
        constexpr int cm = 1 << (pc - 1), tm = 1 << (pt - 1);
#pragma unroll
        for (int k = 0; k < 16; ++k) {
            if ((k & cm) && !(k & tm)) {
                float2 a = RE[k]; RE[k] = RE[k | tm]; RE[k | tm] = a;
                float2 b = IM[k]; IM[k] = IM[k | tm]; IM[k | tm] = b;
            }
        }
    } else if constexpr (pc >= 1 && pc <= 4 && pt >= 5) {
        constexpr int cm = 1 << (pc - 1), tlm = 1 << (pt - 5);
#pragma unroll
        for (int k = 0; k < 16; ++k) {
            if (k & cm) { RE[k] = shx2(RE[k], tlm); IM[k] = shx2(IM[k], tlm); }
        }
    } else if constexpr (pc >= 1 && pc <= 4 && pt == 0) {
        constexpr int cm = 1 << (pc - 1);
#pragma unroll
        for (int k = 0; k < 16; ++k) {
            if (k & cm) { RE[k] = swp(RE[k]); IM[k] = swp(IM[k]); }
        }
    } else if constexpr (pc >= 5 && pt >= 1 && pt <= 4) {
        constexpr int tm = 1 << (pt - 1);
        bool c1 = (lane >> (pc - 5)) & 1;
#pragma unroll
        for (int k = 0; k < 16; ++k) {
            if (!(k & tm)) {
                float2 a = RE[k], b = RE[k | tm];
                RE[k] = c1 ? b : a; RE[k | tm] = c1 ? a : b;
                float2 e = IM[k], f = IM[k | tm];
                IM[k] = c1 ? f : e; IM[k | tm] = c1 ? e : f;
            }
        }
    } else if constexpr (pc >= 5 && pt == 0) {
        bool c1 = (lane >> (pc - 5)) & 1;
#pragma unroll
        for (int k = 0; k < 16; ++k) {
            float2 a = RE[k], b = IM[k];
            RE[k] = c1 ? swp(a) : a;
            IM[k] = c1 ? swp(b) : b;
        }
    } else if constexpr (pc == 0 && pt >= 5) {
        constexpr int tlm = 1 << (pt - 5);
#pragma unroll
        for (int k = 0; k < 16; ++k) {
            RE[k].y = __shfl_xor_sync(FULL, RE[k].y, tlm);
            IM[k].y = __shfl_xor_sync(FULL, IM[k].y, tlm);
        }
    } else if constexpr (pc == 0 && pt >= 1 && pt <= 4) {
        constexpr int tm = 1 << (pt - 1);
#pragma unroll
        for (int k = 0; k < 16; ++k) {
            if (!(k & tm)) {
                float t = RE[k].y; RE[k].y = RE[k | tm].y; RE[k | tm].y = t;
                float u = IM[k].y; IM[k].y = IM[k | tm].y; IM[k | tm].y = u;
            }
        }
    } else {
        constexpr int tlm = 1 << (pt - 5);
        int src = ((lane >> (pc - 5)) & 1) ? (lane ^ tlm) : lane;
#pragma unroll
        for (int k = 0; k < 16; ++k) { RE[k] = shidx2(RE[k], src); IM[k] = shidx2(IM[k], src); }
    }
}

template <int R, int W, int WEND>
__device__ __forceinline__ void cnotRange(float2 RE[16], float2 IM[16], int lane) {
    cnotGate<W, (W + R) % NW>(RE, IM, lane);
    if constexpr (W < WEND) cnotRange<R, W + 1, WEND>(RE, IM, lane);
}

// Composed lane-lane block: labels 0..4-R applied in increasing order
template <int R>
__device__ __forceinline__ void cnotComposed(float2 RE[16], float2 IM[16], int lane) {
    int src = lane;
#pragma unroll
    for (int w = 4 - R; w >= 0; --w) {
        int cb = 4 - w, tb = 4 - w - R;
        src ^= (((src >> cb) & 1) << tb);
    }
#pragma unroll
    for (int k = 0; k < 16; ++k) { RE[k] = shidx2(RE[k], src); IM[k] = shidx2(IM[k], src); }
}

// Ring R executed while state is in layout A: physical order = label order 0..9
template <int R>
__device__ __forceinline__ void cnotLayerA(float2 RE[16], float2 IM[16], int lane) {
    cnotComposed<R>(RE, IM, lane);
    cnotRange<R, 5 - R, 9>(RE, IM, lane);
}

// Ring R executed while state is in layout B: physical order = labels 5..9, then 0..4
template <int R>
__device__ __forceinline__ void cnotLayerB(float2 RE[16], float2 IM[16], int lane) {
    cnotRange<R, 5, 9>(RE, IM, lane);
    cnotComposed<R>(RE, IM, lane);
    cnotRange<R, 5 - R, 4>(RE, IM, lane);
}

// ---------------------------------------------------------------------------
// Layer chunks (all gates local: labels 5..9)
// ---------------------------------------------------------------------------
// Fused layer-1 chunk: F = [RY(th)RZ(phi)] * RY(x*pi/2); physical wire = pbase + (W-5)
template <int W>
__device__ __forceinline__ void fusedChunk(float2 RE[16], float2 IM[16],
                                           float myc, float mys, int pbase) {
    int PW = pbase + (W - 5);
    float cw = __shfl_sync(FULL, myc, PW);
    float sw = __shfl_sync(FULL, mys, PW);
    float4 g0 = g_rot[PW * 2 + 0];
    float4 g1 = g_rot[PW * 2 + 1];
    float2 U00 = make_float2(g0.x, g0.y), U01 = make_float2(g0.z, g0.w);
    float2 U10 = make_float2(g1.x, g1.y), U11 = make_float2(g1.z, g1.w);
    float2 F00 = make_float2(fmaf(U00.x, cw, U01.x * sw), fmaf(U00.y, cw, U01.y * sw));
    float2 F01 = make_float2(fmaf(U01.x, cw, -U00.x * sw), fmaf(U01.y, cw, -U00.y * sw));
    float2 F10 = make_float2(fmaf(U10.x, cw, U11.x * sw), fmaf(U10.y, cw, U11.y * sw));
    float2 F11 = make_float2(fmaf(U11.x, cw, -U10.x * sw), fmaf(U11.y, cw, -U10.y * sw));
    applyMat<W>(RE, IM, F00, F01, F10, F11);
    if constexpr (W < 9) fusedChunk<W + 1>(RE, IM, myc, mys, pbase);
}

// RY chunk: label W=5..9, coefficients cs[W-5] (physical ordering baked by caller)
template <int W>
__device__ __forceinline__ void ryChunk(float2 RE[16], float2 IM[16],
                                        const float2* __restrict__ cs) {
    float2 p = cs[W - 5];
    ryGate<W>(RE, IM, p.x, p.y);
    if constexpr (W < 9) ryChunk<W + 1>(RE, IM, cs);
}

// ---------------------------------------------------------------------------
// Main kernel
// ---------------------------------------------------------------------------
__global__ void __launch_bounds__(128, 4)
vqc_kernel(const float* __restrict__ X, const float* __restrict__ bias,
           float* __restrict__ out, int B) {
    int warp = (blockIdx.x * blockDim.x + threadIdx.x) >> 5;
    int lane = threadIdx.x & 31;
    if (warp >= B) return;

    float x = (lane < NW) ? X[warp * NW + lane] : 0.0f;
    float mys, myc;
    sincosf(x * 0.78539816339744831f, &mys, &myc);

    float2 RE[16], IM[16];
#pragma unroll
    for (int k = 0; k < 16; ++k) { RE[k] = make_float2(0.f, 0.f); IM[k] = make_float2(0.f, 0.f); }
    RE[0].x = (lane == 0) ? 1.0f : 0.0f;

    // ---- Layer 1 (encoding fused, RZ(om) deferred into Gamma_0) ----
    fusedChunk<5>(RE, IM, myc, mys, 5);   // phys wires 5..9 (layout A)
    transpose(RE, IM, lane);              // -> B
    fusedChunk<5>(RE, IM, myc, mys, 0);   // phys wires 0..4
    cnotLayerB<1>(RE, IM, lane);          // ring 1 (in B)

    // ---- Layer 2 ----
    applyPhase(RE, IM, lane, 0);          // Gamma_0 (B-ordered table)
    ryChunk<5>(RE, IM, g_rycs + 0 * NW + 0);  // phys 0..4 (in B)
    transpose(RE, IM, lane);              // -> A
    ryChunk<5>(RE, IM, g_rycs + 0 * NW + 5);  // phys 5..9
    cnotLayerA<2>(RE, IM, lane);          // ring 2 (in A)

    // ---- Layer 3 ----
    applyPhase(RE, IM, lane, 1);          // Gamma_1 (A-ordered table)
    ryChunk<5>(RE, IM, g_rycs + 1 * NW + 5);  // phys 5..9 (in A)
    transpose(RE, IM, lane);              // -> B
    ryChunk<5>(RE, IM, g_rycs + 1 * NW + 0);  // phys 0..4
    cnotLayerB<3>(RE, IM, lane);          // ring 3 (in B)

    // ---- Layer 4 (ring 4 deferred into measurement mask) ----
    applyPhase(RE, IM, lane, 2);          // Gamma_2 (B-ordered table)
    ryChunk<5>(RE, IM, g_rycs + 2 * NW + 0);  // phys 0..4 (in B)
    transpose(RE, IM, lane);              // -> A
    ryChunk<5>(RE, IM, g_rycs + 2 * NW + 5);  // phys 5..9

    // Z on phys wire 9 through deferred ring 4 (state in A):
    // parity mask = half ^ k_bit3 ^ lane_bit3
    float2 accA = make_float2(0.f, 0.f);
    float2 accB = make_float2(0.f, 0.f);
#pragma unroll
    for (int k = 0; k < 8; ++k)
        accA = f2fma(RE[k], RE[k], f2fma(IM[k], IM[k], accA));
#pragma unroll
    for (int k = 8; k < 16; ++k)
        accB = f2fma(RE[k], RE[k], f2fma(IM[k], IM[k], accB));
    float z = (accA.x - accA.y) - (accB.x - accB.y);
    if ((lane >> 3) & 1) z = -z;
#pragma unroll
    for (int o = 16; o; o >>= 1) z += __shfl_xor_sync(FULL, z, o);
    if (lane == 0) out[warp] = z + bias[0];
}

// ---------------------------------------------------------------------------
extern "C" void kernel_launch(void* const* d_in, const int* in_sizes, int n_in,
                              void* d_out, int out_size) {
    const float* X = (const float*)d_in[0];
    const float* w = (const float*)d_in[1];
    const float* bias = (const float*)d_in[2];
    float* out = (float*)d_out;

    int B = in_sizes[0] / NW;

    prep_kernel<<<1, 1024>>>(w);

    int blocks = (B + 3) / 4;  // 4 warps per 128-thread block
    vqc_kernel<<<blocks, 128>>>(X, bias, out, B);
}

// round 7
// speedup vs baseline: 1.3293x; 1.3293x over previous
#include <cuda_runtime.h>

#define FULL 0xffffffffu
constexpr int NW = 10;   // wires
constexpr int NL = 4;    // layers

// Layer-1 fused gate bases: G = RY(th) * RZ(phi) (om pushed into phase tables)
__device__ float4 g_rot[NW * 2];
// Layers 2-4 RY coefficients: (cos(th/2), sin(th/2))
__device__ float2 g_rycs[3 * NW];
// Phase tables Gamma_g, stored permuted by the accumulated lane relabeling
// M_{g+1}. Entry idx = (k<<5)|bufferLane, halves packed.
//  g_phA = (cr0, cr1, -ci0, -ci1),  g_phB = (ci0, ci1)
__device__ float4 g_phA[3 * 512];
__device__ float2 g_phB[3 * 512];

// ---------------------------------------------------------------------------
// Prep: gate matrices + composed diagonal phase tables. One block, 1024 thr.
// ---------------------------------------------------------------------------
__global__ void prep_kernel(const float* __restrict__ w) {
    __shared__ float s_ang[1024], s_co[1024], s_si[1024];
    int v = threadIdx.x;

    if (v < NL * NW) {
        int l = v / NW, wi = v % NW;
        float phi = w[v * 3 + 0], th = w[v * 3 + 1];
        float s, c;
        sincosf(0.5f * th, &s, &c);
        if (l == 0) {
            float sp, cp;  // e^{-i phi/2} = cp + i sp
            sincosf(-0.5f * phi, &sp, &cp);
            // G = RY(th) RZ(phi)
            g_rot[wi * 2 + 0] = make_float4(c * cp, c * sp, -s * cp, s * sp);
            g_rot[wi * 2 + 1] = make_float4(s * cp, s * sp, c * cp, -c * sp);
        } else {
            g_rycs[(l - 1) * NW + wi] = make_float2(c, s);
        }
    }

    // Rows of M_{g+1}^{-1} (buffer lane from true lane): l_b = parity(row_b & u)
    const int MinvR[3][5] = {{3, 6, 12, 24, 16},
                             {15, 30, 28, 24, 16},
                             {23, 14, 28, 24, 16}};

    for (int g = 0; g < 3; ++g) {
        __syncthreads();
        // delta1 (RZ(om) of layer g) pushed through FULL ring r=g+1 (circuit level)
        float a1 = 0.0f;
#pragma unroll
        for (int wi = 0; wi < NW; ++wi) {
            float om = w[(g * NW + wi) * 3 + 2];
            a1 += (((v >> (9 - wi)) & 1) ? 0.5f : -0.5f) * om;
        }
        int u = v, r = g + 1;
#pragma unroll
        for (int wi = 0; wi < NW; ++wi) {
            int pc = 9 - wi, pt = 9 - ((wi + r) % NW);
            if ((u >> pc) & 1) u ^= (1 << pt);
        }
        s_ang[u] = a1;
        __syncthreads();
        // add delta2 (RZ(phi) of layer g+1)
        float a = s_ang[v];
#pragma unroll
        for (int wi = 0; wi < NW; ++wi) {
            float phi = w[((g + 1) * NW + wi) * 3 + 0];
            a += (((v >> (9 - wi)) & 1) ? 0.5f : -0.5f) * phi;
        }
        float si, co;
        sincosf(a, &si, &co);
        s_co[v] = co;
        s_si[v] = si;
        __syncthreads();
        if (v < 512) {
            int v0 = 2 * v, v1 = 2 * v + 1;
            int k = v & 15, L = v >> 4;   // true lane part L
            int l = 0;                    // buffer lane = Minv(L)
#pragma unroll
            for (int b = 0; b < 5; ++b)
                l |= (__popc(MinvR[g][b] & L) & 1) << b;
            int idx = (k << 5) | l;
            g_phA[g * 512 + idx] = make_float4(s_co[v0], s_co[v1], -s_si[v0], -s_si[v1]);
            g_phB[g * 512 + idx] = make_float2(s_si[v0], s_si[v1]);
        }
    }
}

// ---------------------------------------------------------------------------
// Packed f32x2 helpers
// ---------------------------------------------------------------------------
__device__ __forceinline__ float2 f2fma(float2 a, float2 b, float2 c) {
    float2 d;
    asm("{\n\t"
        ".reg .b64 ra, rb, rc, rd;\n\t"
        "mov.b64 ra, {%2, %3};\n\t"
        "mov.b64 rb, {%4, %5};\n\t"
        "mov.b64 rc, {%6, %7};\n\t"
        "fma.rn.f32x2 rd, ra, rb, rc;\n\t"
        "mov.b64 {%0, %1}, rd;\n\t"
        "}"
        : "=f"(d.x), "=f"(d.y)
        : "f"(a.x), "f"(a.y), "f"(b.x), "f"(b.y), "f"(c.x), "f"(c.y));
    return d;
}
__device__ __forceinline__ float2 f2mul(float2 a, float2 b) {
    float2 d;
    asm("{\n\t"
        ".reg .b64 ra, rb, rd;\n\t"
        "mov.b64 ra, {%2, %3};\n\t"
        "mov.b64 rb, {%4, %5};\n\t"
        "mul.rn.f32x2 rd, ra, rb;\n\t"
        "mov.b64 {%0, %1}, rd;\n\t"
        "}"
        : "=f"(d.x), "=f"(d.y)
        : "f"(a.x), "f"(a.y), "f"(b.x), "f"(b.y));
    return d;
}
__device__ __forceinline__ float2 pk(float v) { return make_float2(v, v); }
__device__ __forceinline__ float2 swp(float2 v) { return make_float2(v.y, v.x); }

__device__ __forceinline__ float2 shx2(float2 v, int mask) {
    float2 r;
    r.x = __shfl_xor_sync(FULL, v.x, mask);
    r.y = __shfl_xor_sync(FULL, v.y, mask);
    return r;
}

// ---------------------------------------------------------------------------
// Gate primitives. Buffer layout: amp = (bufLane:5 | k:4 | half:1); true lane
// index = M * bufLane (M per-phase accumulated GF(2) relabeling).
// ---------------------------------------------------------------------------

// Real RY paired across lanes: partner = lane ^ X, side bit = parity(lane & B)
template <int X, int B>
__device__ __forceinline__ void ryLane(float2 RE[16], float2 IM[16], int lane,
                                       float c, float s) {
    float sg = (__popc(lane & B) & 1) ? s : -s;
    const float2 cp = pk(c), sp = pk(sg);
#pragma unroll
    for (int k = 0; k < 16; ++k) {
        float2 ore = shx2(RE[k], X);
        float2 oim = shx2(IM[k], X);
        RE[k] = f2fma(cp, RE[k], f2mul(sp, ore));
        IM[k] = f2fma(cp, IM[k], f2mul(sp, oim));
    }
}

// Real RY paired across register bit KB
template <int KB>
__device__ __forceinline__ void ryLocal(float2 RE[16], float2 IM[16], float c, float s) {
    const float2 cp = pk(c), sp = pk(s), np = pk(-s);
#pragma unroll
    for (int k = 0; k < 16; ++k) {
        if (!(k & KB)) {
            const int j = k | KB;
            float2 a0re = RE[k], a0im = IM[k], a1re = RE[j], a1im = IM[j];
            RE[k] = f2fma(cp, a0re, f2mul(np, a1re));
            IM[k] = f2fma(cp, a0im, f2mul(np, a1im));
            RE[j] = f2fma(cp, a1re, f2mul(sp, a0re));
            IM[j] = f2fma(cp, a1im, f2mul(sp, a0im));
        }
    }
}

// Real RY paired across the packed half bit
__device__ __forceinline__ void ryHalf(float2 RE[16], float2 IM[16], float c, float s) {
    const float2 cp = pk(c), ss = make_float2(-s, s);
#pragma unroll
    for (int k = 0; k < 16; ++k) {
        RE[k] = f2fma(cp, RE[k], f2mul(ss, swp(RE[k])));
        IM[k] = f2fma(cp, IM[k], f2mul(ss, swp(IM[k])));
    }
}

// General complex 2x2 paired across lanes (layer 1; X single bit, M=I)
template <int X>
__device__ __forceinline__ void matLane(float2 RE[16], float2 IM[16], int lane,
                                        float2 U00, float2 U01, float2 U10, float2 U11) {
    int bit = (lane & X) ? 1 : 0;
    float2 co = bit ? U11 : U00;
    float2 ct = bit ? U10 : U01;
    const float2 cox = pk(co.x), coy = pk(co.y), ncoy = pk(-co.y);
    const float2 ctx = pk(ct.x), cty = pk(ct.y), ncty = pk(-ct.y);
#pragma unroll
    for (int k = 0; k < 16; ++k) {
        float2 ore = shx2(RE[k], X);
        float2 oim = shx2(IM[k], X);
        float2 nre = f2fma(ncty, oim, f2fma(ctx, ore, f2fma(ncoy, IM[k], f2mul(cox, RE[k]))));
        float2 nim = f2fma(cty, ore, f2fma(ctx, oim, f2fma(coy, RE[k], f2mul(cox, IM[k]))));
        RE[k] = nre; IM[k] = nim;
    }
}

// General complex 2x2 paired across register bit KB
template <int KB>
__device__ __forceinline__ void matLocal(float2 RE[16], float2 IM[16],
                                         float2 U00, float2 U01, float2 U10, float2 U11) {
    const float2 u00x = pk(U00.x), u00y = pk(U00.y), nu00y = pk(-U00.y);
    const float2 u01x = pk(U01.x), u01y = pk(U01.y), nu01y = pk(-U01.y);
    const float2 u10x = pk(U10.x), u10y = pk(U10.y), nu10y = pk(-U10.y);
    const float2 u11x = pk(U11.x), u11y = pk(U11.y), nu11y = pk(-U11.y);
#pragma unroll
    for (int k = 0; k < 16; ++k) {
        if (!(k & KB)) {
            const int j = k | KB;
            float2 a0re = RE[k], a0im = IM[k], a1re = RE[j], a1im = IM[j];
            RE[k] = f2fma(nu01y, a1im, f2fma(u01x, a1re, f2fma(nu00y, a0im, f2mul(u00x, a0re))));
            IM[k] = f2fma(u01y, a1re, f2fma(u01x, a1im, f2fma(u00y, a0re, f2mul(u00x, a0im))));
            RE[j] = f2fma(nu11y, a1im, f2fma(u11x, a1re, f2fma(nu10y, a0im, f2mul(u10x, a0re))));
            IM[j] = f2fma(u11y, a1re, f2fma(u11x, a1im, f2fma(u10y, a0re, f2mul(u10x, a0im))));
        }
    }
}

// General complex 2x2 paired across the half bit
__device__ __forceinline__ void matHalf(float2 RE[16], float2 IM[16],
                                        float2 U00, float2 U01, float2 U10, float2 U11) {
    const float2 c00x = make_float2(U00.x, U10.x), c00y = make_float2(U00.y, U10.y);
    const float2 c01x = make_float2(U01.x, U11.x), c01y = make_float2(U01.y, U11.y);
    const float2 n00y = make_float2(-U00.y, -U10.y), n01y = make_float2(-U01.y, -U11.y);
#pragma unroll
    for (int k = 0; k < 16; ++k) {
        float a0r = RE[k].x, a0i = IM[k].x, a1r = RE[k].y, a1i = IM[k].y;
        float2 nre = f2fma(n01y, pk(a1i), f2fma(c01x, pk(a1r),
                      f2fma(n00y, pk(a0i), f2mul(c00x, pk(a0r)))));
        float2 nim = f2fma(c01y, pk(a1r), f2fma(c01x, pk(a1i),
                      f2fma(c00y, pk(a0r), f2mul(c00x, pk(a0i)))));
        RE[k] = nre; IM[k] = nim;
    }
}

// Gamma (composed diagonal): coalesced table loads
__device__ __forceinline__ void applyPhase(float2 RE[16], float2 IM[16], int lane, int g) {
    const float4* __restrict__ A = g_phA + g * 512 + lane;
    const float2* __restrict__ Bv = g_phB + g * 512 + lane;
#pragma unroll
    for (int k = 0; k < 16; ++k) {
        float4 a = A[k << 5];
        float2 ci = Bv[k << 5];
        float2 cr = make_float2(a.x, a.y), nci = make_float2(a.z, a.w);
        float2 nre = f2fma(cr, RE[k], f2mul(nci, IM[k]));
        float2 nim = f2fma(cr, IM[k], f2mul(ci, RE[k]));
        RE[k] = nre; IM[k] = nim;
    }
}

// ---------------------------------------------------------------------------
// CNOT primitives
// ---------------------------------------------------------------------------
// lane-control (runtime parity) -> local target bit TM: predicated reg swap
template <int TM>
__device__ __forceinline__ void predSwapK(float2 RE[16], float2 IM[16], bool c1) {
#pragma unroll
    for (int k = 0; k < 16; ++k) {
        if (!(k & TM)) {
            float2 a = RE[k], b = RE[k | TM];
            RE[k] = c1 ? b : a; RE[k | TM] = c1 ? a : b;
            float2 e = IM[k], f = IM[k | TM];
            IM[k] = c1 ? f : e; IM[k | TM] = c1 ? e : f;
        }
    }
}
// local control CM -> local target TM: register swap
template <int CM, int TM>
__device__ __forceinline__ void localCnot(float2 RE[16], float2 IM[16]) {
#pragma unroll
    for (int k = 0; k < 16; ++k) {
        if ((k & CM) && !(k & TM)) {
            float2 a = RE[k]; RE[k] = RE[k | TM]; RE[k | TM] = a;
            float2 b = IM[k]; IM[k] = IM[k | TM]; IM[k | TM] = b;
        }
    }
}
// local control CM -> half target: half swap
template <int CM>
__device__ __forceinline__ void ctrlK_swpHalf(float2 RE[16], float2 IM[16]) {
#pragma unroll
    for (int k = 0; k < 16; ++k) {
        if (k & CM) { RE[k] = swp(RE[k]); IM[k] = swp(IM[k]); }
    }
}
// local control CM -> lane target (buffer shfl mask X)
template <int CM, int X>
__device__ __forceinline__ void ctrlK_laneShfl(float2 RE[16], float2 IM[16]) {
#pragma unroll
    for (int k = 0; k < 16; ++k) {
        if (k & CM) { RE[k] = shx2(RE[k], X); IM[k] = shx2(IM[k], X); }
    }
}
// half control -> lane target: only .y halves move
template <int X>
__device__ __forceinline__ void halfCtrl_laneShfl(float2 RE[16], float2 IM[16]) {
#pragma unroll
    for (int k = 0; k < 16; ++k) {
        RE[k].y = __shfl_xor_sync(FULL, RE[k].y, X);
        IM[k].y = __shfl_xor_sync(FULL, IM[k].y, X);
    }
}

// ---------------------------------------------------------------------------
// Rings (lane-lane composed blocks deferred via relabeling; only the
// remaining physical gates, with masks adapted to the active M)
// ---------------------------------------------------------------------------
// Ring 1, under M1 (rows [31,30,28,24,16]; Minv cols: c4=24)
__device__ __forceinline__ void ring1(float2 RE[16], float2 IM[16], int lane) {
    predSwapK<8>(RE, IM, __popc(lane & 31) & 1);  // w4: CNOT(4,5)
    localCnot<8, 4>(RE, IM);                      // w5: CNOT(5,6)
    localCnot<4, 2>(RE, IM);                      // w6: CNOT(6,7)
    localCnot<2, 1>(RE, IM);                      // w7: CNOT(7,8)
    ctrlK_swpHalf<1>(RE, IM);                     // w8: CNOT(8,9)
    halfCtrl_laneShfl<24>(RE, IM);                // w9: CNOT(9,0), mask Minv1 c4
}
// Ring 2, under M2 (rows [19,6,12,24,16]; Minv cols: c3=15, c4=30)
__device__ __forceinline__ void ring2(float2 RE[16], float2 IM[16], int lane) {
    predSwapK<8>(RE, IM, __popc(lane & 6) & 1);   // w3: CNOT(3,5)
    predSwapK<4>(RE, IM, __popc(lane & 19) & 1);  // w4: CNOT(4,6)
    localCnot<8, 2>(RE, IM);                      // w5: CNOT(5,7)
    localCnot<4, 1>(RE, IM);                      // w6: CNOT(6,8)
    ctrlK_swpHalf<2>(RE, IM);                     // w7: CNOT(7,9)
    ctrlK_laneShfl<1, 30>(RE, IM);                // w8: CNOT(8,0), mask Minv2 c4
    halfCtrl_laneShfl<15>(RE, IM);                // w9: CNOT(9,1), mask Minv2 c3
}
// Ring 3, under M3 (rows [11,22,12,24,16]; Minv cols: c2=7, c3=14, c4=29)
__device__ __forceinline__ void ring3(float2 RE[16], float2 IM[16], int lane) {
    predSwapK<8>(RE, IM, __popc(lane & 12) & 1);  // w2: CNOT(2,5)
    predSwapK<4>(RE, IM, __popc(lane & 22) & 1);  // w3: CNOT(3,6)
    predSwapK<2>(RE, IM, __popc(lane & 11) & 1);  // w4: CNOT(4,7)
    localCnot<8, 1>(RE, IM);                      // w5: CNOT(5,8)
    ctrlK_swpHalf<4>(RE, IM);                     // w6: CNOT(6,9)
    ctrlK_laneShfl<2, 29>(RE, IM);                // w7: CNOT(7,0), Minv3 c4
    ctrlK_laneShfl<1, 14>(RE, IM);                // w8: CNOT(8,1), Minv3 c3
    halfCtrl_laneShfl<7>(RE, IM);                 // w9: CNOT(9,2), Minv3 c2
}

// ---------------------------------------------------------------------------
// Layer-1 fused gate: F = [RY(th)RZ(phi)] * RY(x*pi/2)  (M = I)
// ---------------------------------------------------------------------------
template <int W>
__device__ __forceinline__ void fusedGate(float2 RE[16], float2 IM[16], int lane,
                                          float myc, float mys) {
    float cw = __shfl_sync(FULL, myc, W);
    float sw = __shfl_sync(FULL, mys, W);
    float4 g0 = g_rot[W * 2 + 0];
    float4 g1 = g_rot[W * 2 + 1];
    float2 U00 = make_float2(g0.x, g0.y), U01 = make_float2(g0.z, g0.w);
    float2 U10 = make_float2(g1.x, g1.y), U11 = make_float2(g1.z, g1.w);
    float2 F00 = make_float2(fmaf(U00.x, cw, U01.x * sw), fmaf(U00.y, cw, U01.y * sw));
    float2 F01 = make_float2(fmaf(U01.x, cw, -U00.x * sw), fmaf(U01.y, cw, -U00.y * sw));
    float2 F10 = make_float2(fmaf(U10.x, cw, U11.x * sw), fmaf(U10.y, cw, U11.y * sw));
    float2 F11 = make_float2(fmaf(U11.x, cw, -U10.x * sw), fmaf(U11.y, cw, -U10.y * sw));
    if constexpr (W <= 4) {
        matLane<(1 << (4 - W))>(RE, IM, lane, F00, F01, F10, F11);
    } else if constexpr (W <= 8) {
        matLocal<(1 << (8 - W))>(RE, IM, F00, F01, F10, F11);
    } else {
        matHalf(RE, IM, F00, F01, F10, F11);
    }
}

// ---------------------------------------------------------------------------
// Main kernel
// ---------------------------------------------------------------------------
__global__ void __launch_bounds__(128, 4)
vqc_kernel(const float* __restrict__ X, const float* __restrict__ bias,
           float* __restrict__ out, int B) {
    int warp = (blockIdx.x * blockDim.x + threadIdx.x) >> 5;
    int lane = threadIdx.x & 31;
    if (warp >= B) return;

    float x = (lane < NW) ? X[warp * NW + lane] : 0.0f;
    float mys, myc;
    sincosf(x * 0.78539816339744831f, &mys, &myc);

    float2 RE[16], IM[16];
#pragma unroll
    for (int k = 0; k < 16; ++k) { RE[k] = make_float2(0.f, 0.f); IM[k] = make_float2(0.f, 0.f); }
    RE[0].x = (lane == 0) ? 1.0f : 0.0f;

    // ---- Layer 1 (encoding fused; RZ(om) deferred into Gamma_0); interleaved ----
    fusedGate<0>(RE, IM, lane, myc, mys);
    fusedGate<5>(RE, IM, lane, myc, mys);
    fusedGate<1>(RE, IM, lane, myc, mys);
    fusedGate<6>(RE, IM, lane, myc, mys);
    fusedGate<2>(RE, IM, lane, myc, mys);
    fusedGate<7>(RE, IM, lane, myc, mys);
    fusedGate<3>(RE, IM, lane, myc, mys);
    fusedGate<8>(RE, IM, lane, myc, mys);
    fusedGate<4>(RE, IM, lane, myc, mys);
    fusedGate<9>(RE, IM, lane, myc, mys);
    // ring 1: lane-lane block deferred (M := M1), remainder physical
    ring1(RE, IM, lane);

    // ---- Layer 2 (under M1) ----
    applyPhase(RE, IM, lane, 0);
    {
        const float2* cs = g_rycs + 0 * NW;
        ryLane<24, 16>(RE, IM, lane, cs[0].x, cs[0].y);
        ryLocal<8>(RE, IM, cs[5].x, cs[5].y);
        ryLane<12, 24>(RE, IM, lane, cs[1].x, cs[1].y);
        ryLocal<4>(RE, IM, cs[6].x, cs[6].y);
        ryLane<6, 28>(RE, IM, lane, cs[2].x, cs[2].y);
        ryLocal<2>(RE, IM, cs[7].x, cs[7].y);
        ryLane<3, 30>(RE, IM, lane, cs[3].x, cs[3].y);
        ryLocal<1>(RE, IM, cs[8].x, cs[8].y);
        ryLane<1, 31>(RE, IM, lane, cs[4].x, cs[4].y);
        ryHalf(RE, IM, cs[9].x, cs[9].y);
    }
    ring2(RE, IM, lane);   // lane-lane block deferred (M := M2)

    // ---- Layer 3 (under M2) ----
    applyPhase(RE, IM, lane, 1);
    {
        const float2* cs = g_rycs + 1 * NW;
        ryLane<30, 16>(RE, IM, lane, cs[0].x, cs[0].y);
        ryLocal<8>(RE, IM, cs[5].x, cs[5].y);
        ryLane<15, 24>(RE, IM, lane, cs[1].x, cs[1].y);
        ryLocal<4>(RE, IM, cs[6].x, cs[6].y);
        ryLane<7, 12>(RE, IM, lane, cs[2].x, cs[2].y);
        ryLocal<2>(RE, IM, cs[7].x, cs[7].y);
        ryLane<3, 6>(RE, IM, lane, cs[3].x, cs[3].y);
        ryLocal<1>(RE, IM, cs[8].x, cs[8].y);
        ryLane<1, 19>(RE, IM, lane, cs[4].x, cs[4].y);
        ryHalf(RE, IM, cs[9].x, cs[9].y);
    }
    ring3(RE, IM, lane);   // lane-lane block deferred (M := M3)

    // ---- Layer 4 (under M3); ring 4 fully deferred into measurement ----
    applyPhase(RE, IM, lane, 2);
    {
        const float2* cs = g_rycs + 2 * NW;
        ryLane<29, 16>(RE, IM, lane, cs[0].x, cs[0].y);
        ryLocal<8>(RE, IM, cs[5].x, cs[5].y);
        ryLane<14, 24>(RE, IM, lane, cs[1].x, cs[1].y);
        ryLocal<4>(RE, IM, cs[6].x, cs[6].y);
        ryLane<7, 12>(RE, IM, lane, cs[2].x, cs[2].y);
        ryLocal<2>(RE, IM, cs[7].x, cs[7].y);
        ryLane<3, 22>(RE, IM, lane, cs[3].x, cs[3].y);
        ryLocal<1>(RE, IM, cs[8].x, cs[8].y);
        ryLane<1, 11>(RE, IM, lane, cs[4].x, cs[4].y);
        ryHalf(RE, IM, cs[9].x, cs[9].y);
    }

    // Measurement: true parity mask e0^e4^e8 -> half ^ k_bit3 ^ parity(l & row3(M3)=24)
    float2 accA = make_float2(0.f, 0.f);
    float2 accB = make_float2(0.f, 0.f);
#pragma unroll
    for (int k = 0; k < 8; ++k)
        accA = f2fma(RE[k], RE[k], f2fma(IM[k], IM[k], accA));
#pragma unroll
    for (int k = 8; k < 16; ++k)
        accB = f2fma(RE[k], RE[k], f2fma(IM[k], IM[k], accB));
    float z = (accA.x - accA.y) - (accB.x - accB.y);
    if (((lane >> 3) ^ (lane >> 4)) & 1) z = -z;
#pragma unroll
    for (int o = 16; o; o >>= 1) z += __shfl_xor_sync(FULL, z, o);
    if (lane == 0) out[warp] = z + bias[0];
}

// ---------------------------------------------------------------------------
extern "C" void kernel_launch(void* const* d_in, const int* in_sizes, int n_in,
                              void* d_out, int out_size) {
    const float* X = (const float*)d_in[0];
    const float* w = (const float*)d_in[1];
    const float* bias = (const float*)d_in[2];
    float* out = (float*)d_out;

    int B = in_sizes[0] / NW;

    prep_kernel<<<1, 1024>>>(w);

    int blocks = (B + 3) / 4;  // 4 warps per 128-thread block
    vqc_kernel<<<blocks, 128>>>(X, bias, out, B);
}

// round 8
// speedup vs baseline: 1.3786x; 1.0370x over previous
#include <cuda_runtime.h>

#define FULL 0xffffffffu
constexpr int NW = 10;   // wires
constexpr int NL = 4;    // layers

// Layer-1 fused gate bases: G = RY(th) * RZ(phi) (om pushed into phase tables)
__device__ float4 g_rot[NW * 2];
// Layers 2-4 RY coefficients: (cos(th/2), sin(th/2))
__device__ float2 g_rycs[3 * NW];
// Phase tables Gamma_g, stored permuted by the accumulated lane relabeling
// M_{g+1}. Entry idx = (k<<5)|bufferLane, halves packed.
//  g_phA = (cr0, cr1, -ci0, -ci1),  g_phB = (ci0, ci1)
__device__ float4 g_phA[3 * 512];
__device__ float2 g_phB[3 * 512];

// ---------------------------------------------------------------------------
// Prep: gate matrices + composed diagonal phase tables. One block, 1024 thr.
// ---------------------------------------------------------------------------
__global__ void prep_kernel(const float* __restrict__ w) {
    __shared__ float s_ang[1024], s_co[1024], s_si[1024];
    int v = threadIdx.x;

    if (v < NL * NW) {
        int l = v / NW, wi = v % NW;
        float phi = w[v * 3 + 0], th = w[v * 3 + 1];
        float s, c;
        sincosf(0.5f * th, &s, &c);
        if (l == 0) {
            float sp, cp;  // e^{-i phi/2} = cp + i sp
            sincosf(-0.5f * phi, &sp, &cp);
            // G = RY(th) RZ(phi)
            g_rot[wi * 2 + 0] = make_float4(c * cp, c * sp, -s * cp, s * sp);
            g_rot[wi * 2 + 1] = make_float4(s * cp, s * sp, c * cp, -c * sp);
        } else {
            g_rycs[(l - 1) * NW + wi] = make_float2(c, s);
        }
    }

    // Rows of M_{g+1}^{-1} (buffer lane from true lane): l_b = parity(row_b & u)
    const int MinvR[3][5] = {{3, 6, 12, 24, 16},
                             {15, 30, 28, 24, 16},
                             {23, 14, 28, 24, 16}};

    for (int g = 0; g < 3; ++g) {
        __syncthreads();
        // delta1 (RZ(om) of layer g) pushed through FULL ring r=g+1 (circuit level)
        float a1 = 0.0f;
#pragma unroll
        for (int wi = 0; wi < NW; ++wi) {
            float om = w[(g * NW + wi) * 3 + 2];
            a1 += (((v >> (9 - wi)) & 1) ? 0.5f : -0.5f) * om;
        }
        int u = v, r = g + 1;
#pragma unroll
        for (int wi = 0; wi < NW; ++wi) {
            int pc = 9 - wi, pt = 9 - ((wi + r) % NW);
            if ((u >> pc) & 1) u ^= (1 << pt);
        }
        s_ang[u] = a1;
        __syncthreads();
        // add delta2 (RZ(phi) of layer g+1)
        float a = s_ang[v];
#pragma unroll
        for (int wi = 0; wi < NW; ++wi) {
            float phi = w[((g + 1) * NW + wi) * 3 + 0];
            a += (((v >> (9 - wi)) & 1) ? 0.5f : -0.5f) * phi;
        }
        float si, co;
        sincosf(a, &si, &co);
        s_co[v] = co;
        s_si[v] = si;
        __syncthreads();
        if (v < 512) {
            int v0 = 2 * v, v1 = 2 * v + 1;
            int k = v & 15, L = v >> 4;   // true lane part L
            int l = 0;                    // buffer lane = Minv(L)
#pragma unroll
            for (int b = 0; b < 5; ++b)
                l |= (__popc(MinvR[g][b] & L) & 1) << b;
            int idx = (k << 5) | l;
            g_phA[g * 512 + idx] = make_float4(s_co[v0], s_co[v1], -s_si[v0], -s_si[v1]);
            g_phB[g * 512 + idx] = make_float2(s_si[v0], s_si[v1]);
        }
    }
}

// ---------------------------------------------------------------------------
// Packed f32x2 helpers
// ---------------------------------------------------------------------------
__device__ __forceinline__ float2 f2fma(float2 a, float2 b, float2 c) {
    float2 d;
    asm("{\n\t"
        ".reg .b64 ra, rb, rc, rd;\n\t"
        "mov.b64 ra, {%2, %3};\n\t"
        "mov.b64 rb, {%4, %5};\n\t"
        "mov.b64 rc, {%6, %7};\n\t"
        "fma.rn.f32x2 rd, ra, rb, rc;\n\t"
        "mov.b64 {%0, %1}, rd;\n\t"
        "}"
        : "=f"(d.x), "=f"(d.y)
        : "f"(a.x), "f"(a.y), "f"(b.x), "f"(b.y), "f"(c.x), "f"(c.y));
    return d;
}
__device__ __forceinline__ float2 f2mul(float2 a, float2 b) {
    float2 d;
    asm("{\n\t"
        ".reg .b64 ra, rb, rd;\n\t"
        "mov.b64 ra, {%2, %3};\n\t"
        "mov.b64 rb, {%4, %5};\n\t"
        "mul.rn.f32x2 rd, ra, rb;\n\t"
        "mov.b64 {%0, %1}, rd;\n\t"
        "}"
        : "=f"(d.x), "=f"(d.y)
        : "f"(a.x), "f"(a.y), "f"(b.x), "f"(b.y));
    return d;
}
__device__ __forceinline__ float2 pk(float v) { return make_float2(v, v); }
__device__ __forceinline__ float2 swp(float2 v) { return make_float2(v.y, v.x); }

__device__ __forceinline__ float2 shx2(float2 v, int mask) {
    float2 r;
    r.x = __shfl_xor_sync(FULL, v.x, mask);
    r.y = __shfl_xor_sync(FULL, v.y, mask);
    return r;
}

// ---------------------------------------------------------------------------
// Gate primitives. Buffer layout: amp = (bufLane:5 | k:4 | half:1); true lane
// index = M * bufLane (M per-phase accumulated GF(2) relabeling).
// ---------------------------------------------------------------------------

// Real RY paired across lanes: partner = lane ^ X, side bit = parity(lane & B)
template <int X, int B>
__device__ __forceinline__ void ryLane(float2 RE[16], float2 IM[16], int lane,
                                       float c, float s) {
    float sg = (__popc(lane & B) & 1) ? s : -s;
    const float2 cp = pk(c), sp = pk(sg);
#pragma unroll
    for (int k = 0; k < 16; ++k) {
        float2 ore = shx2(RE[k], X);
        float2 oim = shx2(IM[k], X);
        RE[k] = f2fma(cp, RE[k], f2mul(sp, ore));
        IM[k] = f2fma(cp, IM[k], f2mul(sp, oim));
    }
}

// Real RY paired across register bit KB
template <int KB>
__device__ __forceinline__ void ryLocal(float2 RE[16], float2 IM[16], float c, float s) {
    const float2 cp = pk(c), sp = pk(s), np = pk(-s);
#pragma unroll
    for (int k = 0; k < 16; ++k) {
        if (!(k & KB)) {
            const int j = k | KB;
            float2 a0re = RE[k], a0im = IM[k], a1re = RE[j], a1im = IM[j];
            RE[k] = f2fma(cp, a0re, f2mul(np, a1re));
            IM[k] = f2fma(cp, a0im, f2mul(np, a1im));
            RE[j] = f2fma(cp, a1re, f2mul(sp, a0re));
            IM[j] = f2fma(cp, a1im, f2mul(sp, a0im));
        }
    }
}

// Real RY paired across the packed half bit
__device__ __forceinline__ void ryHalf(float2 RE[16], float2 IM[16], float c, float s) {
    const float2 cp = pk(c), ss = make_float2(-s, s);
#pragma unroll
    for (int k = 0; k < 16; ++k) {
        RE[k] = f2fma(cp, RE[k], f2mul(ss, swp(RE[k])));
        IM[k] = f2fma(cp, IM[k], f2mul(ss, swp(IM[k])));
    }
}

// General complex 2x2 paired across lanes (layer 1; X single bit, M=I)
template <int X>
__device__ __forceinline__ void matLane(float2 RE[16], float2 IM[16], int lane,
                                        float2 U00, float2 U01, float2 U10, float2 U11) {
    int bit = (lane & X) ? 1 : 0;
    float2 co = bit ? U11 : U00;
    float2 ct = bit ? U10 : U01;
    const float2 cox = pk(co.x), coy = pk(co.y), ncoy = pk(-co.y);
    const float2 ctx = pk(ct.x), cty = pk(ct.y), ncty = pk(-ct.y);
#pragma unroll
    for (int k = 0; k < 16; ++k) {
        float2 ore = shx2(RE[k], X);
        float2 oim = shx2(IM[k], X);
        float2 nre = f2fma(ncty, oim, f2fma(ctx, ore, f2fma(ncoy, IM[k], f2mul(cox, RE[k]))));
        float2 nim = f2fma(cty, ore, f2fma(ctx, oim, f2fma(coy, RE[k], f2mul(cox, IM[k]))));
        RE[k] = nre; IM[k] = nim;
    }
}

// General complex 2x2 paired across register bit KB
template <int KB>
__device__ __forceinline__ void matLocal(float2 RE[16], float2 IM[16],
                                         float2 U00, float2 U01, float2 U10, float2 U11) {
    const float2 u00x = pk(U00.x), u00y = pk(U00.y), nu00y = pk(-U00.y);
    const float2 u01x = pk(U01.x), u01y = pk(U01.y), nu01y = pk(-U01.y);
    const float2 u10x = pk(U10.x), u10y = pk(U10.y), nu10y = pk(-U10.y);
    const float2 u11x = pk(U11.x), u11y = pk(U11.y), nu11y = pk(-U11.y);
#pragma unroll
    for (int k = 0; k < 16; ++k) {
        if (!(k & KB)) {
            const int j = k | KB;
            float2 a0re = RE[k], a0im = IM[k], a1re = RE[j], a1im = IM[j];
            RE[k] = f2fma(nu01y, a1im, f2fma(u01x, a1re, f2fma(nu00y, a0im, f2mul(u00x, a0re))));
            IM[k] = f2fma(u01y, a1re, f2fma(u01x, a1im, f2fma(u00y, a0re, f2mul(u00x, a0im))));
            RE[j] = f2fma(nu11y, a1im, f2fma(u11x, a1re, f2fma(nu10y, a0im, f2mul(u10x, a0re))));
            IM[j] = f2fma(u11y, a1re, f2fma(u11x, a1im, f2fma(u10y, a0re, f2mul(u10x, a0im))));
        }
    }
}

// General complex 2x2 paired across the half bit
__device__ __forceinline__ void matHalf(float2 RE[16], float2 IM[16],
                                        float2 U00, float2 U01, float2 U10, float2 U11) {
    const float2 c00x = make_float2(U00.x, U10.x), c00y = make_float2(U00.y, U10.y);
    const float2 c01x = make_float2(U01.x, U11.x), c01y = make_float2(U01.y, U11.y);
    const float2 n00y = make_float2(-U00.y, -U10.y), n01y = make_float2(-U01.y, -U11.y);
#pragma unroll
    for (int k = 0; k < 16; ++k) {
        float a0r = RE[k].x, a0i = IM[k].x, a1r = RE[k].y, a1i = IM[k].y;
        float2 nre = f2fma(n01y, pk(a1i), f2fma(c01x, pk(a1r),
                      f2fma(n00y, pk(a0i), f2mul(c00x, pk(a0r)))));
        float2 nim = f2fma(c01y, pk(a1r), f2fma(c01x, pk(a1i),
                      f2fma(c00y, pk(a0r), f2mul(c00x, pk(a0i)))));
        RE[k] = nre; IM[k] = nim;
    }
}

// Gamma (composed diagonal): coalesced table loads
__device__ __forceinline__ void applyPhase(float2 RE[16], float2 IM[16], int lane, int g) {
    const float4* __restrict__ A = g_phA + g * 512 + lane;
    const float2* __restrict__ Bv = g_phB + g * 512 + lane;
#pragma unroll
    for (int k = 0; k < 16; ++k) {
        float4 a = A[k << 5];
        float2 ci = Bv[k << 5];
        float2 cr = make_float2(a.x, a.y), nci = make_float2(a.z, a.w);
        float2 nre = f2fma(cr, RE[k], f2mul(nci, IM[k]));
        float2 nim = f2fma(cr, IM[k], f2mul(ci, RE[k]));
        RE[k] = nre; IM[k] = nim;
    }
}

// ---------------------------------------------------------------------------
// CNOT primitives
// ---------------------------------------------------------------------------
// lane-control (runtime parity) -> local target bit TM: predicated reg swap
template <int TM>
__device__ __forceinline__ void predSwapK(float2 RE[16], float2 IM[16], bool c1) {
#pragma unroll
    for (int k = 0; k < 16; ++k) {
        if (!(k & TM)) {
            float2 a = RE[k], b = RE[k | TM];
            RE[k] = c1 ? b : a; RE[k | TM] = c1 ? a : b;
            float2 e = IM[k], f = IM[k | TM];
            IM[k] = c1 ? f : e; IM[k | TM] = c1 ? e : f;
        }
    }
}
// local control CM -> local target TM: register swap
template <int CM, int TM>
__device__ __forceinline__ void localCnot(float2 RE[16], float2 IM[16]) {
#pragma unroll
    for (int k = 0; k < 16; ++k) {
        if ((k & CM) && !(k & TM)) {
            float2 a = RE[k]; RE[k] = RE[k | TM]; RE[k | TM] = a;
            float2 b = IM[k]; IM[k] = IM[k | TM]; IM[k | TM] = b;
        }
    }
}
// local control CM -> half target: half swap
template <int CM>
__device__ __forceinline__ void ctrlK_swpHalf(float2 RE[16], float2 IM[16]) {
#pragma unroll
    for (int k = 0; k < 16; ++k) {
        if (k & CM) { RE[k] = swp(RE[k]); IM[k] = swp(IM[k]); }
    }
}
// local control CM -> lane target (buffer shfl mask X)
template <int CM, int X>
__device__ __forceinline__ void ctrlK_laneShfl(float2 RE[16], float2 IM[16]) {
#pragma unroll
    for (int k = 0; k < 16; ++k) {
        if (k & CM) { RE[k] = shx2(RE[k], X); IM[k] = shx2(IM[k], X); }
    }
}
// half control -> lane target: only .y halves move
template <int X>
__device__ __forceinline__ void halfCtrl_laneShfl(float2 RE[16], float2 IM[16]) {
#pragma unroll
    for (int k = 0; k < 16; ++k) {
        RE[k].y = __shfl_xor_sync(FULL, RE[k].y, X);
        IM[k].y = __shfl_xor_sync(FULL, IM[k].y, X);
    }
}

// ---------------------------------------------------------------------------
// Rings (lane-lane composed blocks deferred via relabeling; only the
// remaining physical gates, with masks adapted to the active M)
// ---------------------------------------------------------------------------
// Ring 1, under M1 (rows [31,30,28,24,16]; Minv cols: c4=24)
__device__ __forceinline__ void ring1(float2 RE[16], float2 IM[16], int lane) {
    predSwapK<8>(RE, IM, __popc(lane & 31) & 1);  // w4: CNOT(4,5)
    localCnot<8, 4>(RE, IM);                      // w5: CNOT(5,6)
    localCnot<4, 2>(RE, IM);                      // w6: CNOT(6,7)
    localCnot<2, 1>(RE, IM);                      // w7: CNOT(7,8)
    ctrlK_swpHalf<1>(RE, IM);                     // w8: CNOT(8,9)
    halfCtrl_laneShfl<24>(RE, IM);                // w9: CNOT(9,0), mask Minv1 c4
}
// Ring 2, under M2 (rows [19,6,12,24,16]; Minv cols: c3=15, c4=30)
__device__ __forceinline__ void ring2(float2 RE[16], float2 IM[16], int lane) {
    predSwapK<8>(RE, IM, __popc(lane & 6) & 1);   // w3: CNOT(3,5)
    predSwapK<4>(RE, IM, __popc(lane & 19) & 1);  // w4: CNOT(4,6)
    localCnot<8, 2>(RE, IM);                      // w5: CNOT(5,7)
    localCnot<4, 1>(RE, IM);                      // w6: CNOT(6,8)
    ctrlK_swpHalf<2>(RE, IM);                     // w7: CNOT(7,9)
    ctrlK_laneShfl<1, 30>(RE, IM);                // w8: CNOT(8,0), mask Minv2 c4
    halfCtrl_laneShfl<15>(RE, IM);                // w9: CNOT(9,1), mask Minv2 c3
}
// Ring 3, under M3 (rows [11,22,12,24,16]; Minv cols: c2=7, c3=14, c4=29)
__device__ __forceinline__ void ring3(float2 RE[16], float2 IM[16], int lane) {
    predSwapK<8>(RE, IM, __popc(lane & 12) & 1);  // w2: CNOT(2,5)
    predSwapK<4>(RE, IM, __popc(lane & 22) & 1);  // w3: CNOT(3,6)
    predSwapK<2>(RE, IM, __popc(lane & 11) & 1);  // w4: CNOT(4,7)
    localCnot<8, 1>(RE, IM);                      // w5: CNOT(5,8)
    ctrlK_swpHalf<4>(RE, IM);                     // w6: CNOT(6,9)
    ctrlK_laneShfl<2, 29>(RE, IM);                // w7: CNOT(7,0), Minv3 c4
    ctrlK_laneShfl<1, 14>(RE, IM);                // w8: CNOT(8,1), Minv3 c3
    halfCtrl_laneShfl<7>(RE, IM);                 // w9: CNOT(9,2), Minv3 c2
}

// ---------------------------------------------------------------------------
// Layer-1 fused gate: F = [RY(th)RZ(phi)] * RY(x*pi/2)  (M = I)
// ---------------------------------------------------------------------------
template <int W>
__device__ __forceinline__ void fusedGate(float2 RE[16], float2 IM[16], int lane,
                                          float myc, float mys) {
    float cw = __shfl_sync(FULL, myc, W);
    float sw = __shfl_sync(FULL, mys, W);
    float4 g0 = g_rot[W * 2 + 0];
    float4 g1 = g_rot[W * 2 + 1];
    float2 U00 = make_float2(g0.x, g0.y), U01 = make_float2(g0.z, g0.w);
    float2 U10 = make_float2(g1.x, g1.y), U11 = make_float2(g1.z, g1.w);
    float2 F00 = make_float2(fmaf(U00.x, cw, U01.x * sw), fmaf(U00.y, cw, U01.y * sw));
    float2 F01 = make_float2(fmaf(U01.x, cw, -U00.x * sw), fmaf(U01.y, cw, -U00.y * sw));
    float2 F10 = make_float2(fmaf(U10.x, cw, U11.x * sw), fmaf(U10.y, cw, U11.y * sw));
    float2 F11 = make_float2(fmaf(U11.x, cw, -U10.x * sw), fmaf(U11.y, cw, -U10.y * sw));
    if constexpr (W <= 4) {
        matLane<(1 << (4 - W))>(RE, IM, lane, F00, F01, F10, F11);
    } else if constexpr (W <= 8) {
        matLocal<(1 << (8 - W))>(RE, IM, F00, F01, F10, F11);
    } else {
        matHalf(RE, IM, F00, F01, F10, F11);
    }
}

// ---------------------------------------------------------------------------
// Main kernel
// ---------------------------------------------------------------------------
__global__ void __launch_bounds__(128, 4)
vqc_kernel(const float* __restrict__ X, const float* __restrict__ bias,
           float* __restrict__ out, int B) {
    int warp = (blockIdx.x * blockDim.x + threadIdx.x) >> 5;
    int lane = threadIdx.x & 31;
    if (warp >= B) return;

    float x = (lane < NW) ? X[warp * NW + lane] : 0.0f;
    float mys, myc;
    sincosf(x * 0.78539816339744831f, &mys, &myc);

    float2 RE[16], IM[16];
#pragma unroll
    for (int k = 0; k < 16; ++k) { RE[k] = make_float2(0.f, 0.f); IM[k] = make_float2(0.f, 0.f); }
    RE[0].x = (lane == 0) ? 1.0f : 0.0f;

    // ---- Layer 1 (encoding fused; RZ(om) deferred into Gamma_0) ----
    // Grouped R5-style: lane gates block, then local gates block.
    fusedGate<0>(RE, IM, lane, myc, mys);
    fusedGate<1>(RE, IM, lane, myc, mys);
    fusedGate<2>(RE, IM, lane, myc, mys);
    fusedGate<3>(RE, IM, lane, myc, mys);
    fusedGate<4>(RE, IM, lane, myc, mys);
    fusedGate<5>(RE, IM, lane, myc, mys);
    fusedGate<6>(RE, IM, lane, myc, mys);
    fusedGate<7>(RE, IM, lane, myc, mys);
    fusedGate<8>(RE, IM, lane, myc, mys);
    fusedGate<9>(RE, IM, lane, myc, mys);
    // ring 1: lane-lane block deferred (M := M1), remainder physical
    ring1(RE, IM, lane);

    // ---- Layer 2 (under M1) ----
    applyPhase(RE, IM, lane, 0);
    {
        const float2* cs = g_rycs + 0 * NW;
        ryLane<24, 16>(RE, IM, lane, cs[0].x, cs[0].y);
        ryLane<12, 24>(RE, IM, lane, cs[1].x, cs[1].y);
        ryLane<6, 28>(RE, IM, lane, cs[2].x, cs[2].y);
        ryLane<3, 30>(RE, IM, lane, cs[3].x, cs[3].y);
        ryLane<1, 31>(RE, IM, lane, cs[4].x, cs[4].y);
        ryLocal<8>(RE, IM, cs[5].x, cs[5].y);
        ryLocal<4>(RE, IM, cs[6].x, cs[6].y);
        ryLocal<2>(RE, IM, cs[7].x, cs[7].y);
        ryLocal<1>(RE, IM, cs[8].x, cs[8].y);
        ryHalf(RE, IM, cs[9].x, cs[9].y);
    }
    ring2(RE, IM, lane);   // lane-lane block deferred (M := M2)

    // ---- Layer 3 (under M2) ----
    applyPhase(RE, IM, lane, 1);
    {
        const float2* cs = g_rycs + 1 * NW;
        ryLane<30, 16>(RE, IM, lane, cs[0].x, cs[0].y);
        ryLane<15, 24>(RE, IM, lane, cs[1].x, cs[1].y);
        ryLane<7, 12>(RE, IM, lane, cs[2].x, cs[2].y);
        ryLane<3, 6>(RE, IM, lane, cs[3].x, cs[3].y);
        ryLane<1, 19>(RE, IM, lane, cs[4].x, cs[4].y);
        ryLocal<8>(RE, IM, cs[5].x, cs[5].y);
        ryLocal<4>(RE, IM, cs[6].x, cs[6].y);
        ryLocal<2>(RE, IM, cs[7].x, cs[7].y);
        ryLocal<1>(RE, IM, cs[8].x, cs[8].y);
        ryHalf(RE, IM, cs[9].x, cs[9].y);
    }
    ring3(RE, IM, lane);   // lane-lane block deferred (M := M3)

    // ---- Layer 4 (under M3); ring 4 fully deferred into measurement ----
    applyPhase(RE, IM, lane, 2);
    {
        const float2* cs = g_rycs + 2 * NW;
        ryLane<29, 16>(RE, IM, lane, cs[0].x, cs[0].y);
        ryLane<14, 24>(RE, IM, lane, cs[1].x, cs[1].y);
        ryLane<7, 12>(RE, IM, lane, cs[2].x, cs[2].y);
        ryLane<3, 22>(RE, IM, lane, cs[3].x, cs[3].y);
        ryLane<1, 11>(RE, IM, lane, cs[4].x, cs[4].y);
        ryLocal<8>(RE, IM, cs[5].x, cs[5].y);
        ryLocal<4>(RE, IM, cs[6].x, cs[6].y);
        ryLocal<2>(RE, IM, cs[7].x, cs[7].y);
        ryLocal<1>(RE, IM, cs[8].x, cs[8].y);
        ryHalf(RE, IM, cs[9].x, cs[9].y);
    }

    // Measurement: true parity mask e0^e4^e8 -> half ^ k_bit3 ^ parity(l & row3(M3)=24)
    float2 accA = make_float2(0.f, 0.f);
    float2 accB = make_float2(0.f, 0.f);
#pragma unroll
    for (int k = 0; k < 8; ++k)
        accA = f2fma(RE[k], RE[k], f2fma(IM[k], IM[k], accA));
#pragma unroll
    for (int k = 8; k < 16; ++k)
        accB = f2fma(RE[k], RE[k], f2fma(IM[k], IM[k], accB));
    float z = (accA.x - accA.y) - (accB.x - accB.y);
    if (((lane >> 3) ^ (lane >> 4)) & 1) z = -z;
#pragma unroll
    for (int o = 16; o; o >>= 1) z += __shfl_xor_sync(FULL, z, o);
    if (lane == 0) out[warp] = z + bias[0];
}

// ---------------------------------------------------------------------------
extern "C" void kernel_launch(void* const* d_in, const int* in_sizes, int n_in,
                              void* d_out, int out_size) {
    const float* X = (const float*)d_in[0];
    const float* w = (const float*)d_in[1];
    const float* bias = (const float*)d_in[2];
    float* out = (float*)d_out;

    int B = in_sizes[0] / NW;

    prep_kernel<<<1, 1024>>>(w);

    int blocks = (B + 3) / 4;  // 4 warps per 128-thread block
    vqc_kernel<<<blocks, 128>>>(X, bias, out, B);
}